// round 3
// baseline (speedup 1.0000x reference)
#include <cuda_runtime.h>
#include <math.h>

// Problem constants
// x: (2, 8, 512, 256, 8), prev_qk: (2,8,8,512,512), conv w: (8,8,3,3), w*: (8,256,256)
// out = out(2,8,512,256,8) then qk(2,8,8,512,512)

#define QK_OFF 16777216ull   // elements in 'out'

// ---------------- scratch (device globals; no allocation allowed) ----------------
// conv outputs: [qkv][n=1024][c=8][h=256][w=8]
__device__ float g_conv[3u * 1024u * 8u * 256u * 8u];          // 50,331,648 floats
// q,k,v in head layout: [(b*8+c)*8+nh][l=512][d=256]
__device__ float g_q[128u * 512u * 256u];
__device__ float g_k[128u * 512u * 256u];
__device__ float g_v[128u * 512u * 256u];
// attention output, stored as [(b*8+c)][l][h=256][w=8] for the output projection
__device__ float g_a[16u * 512u * 2048u];
// softmax row stats: [head*512 + l]
__device__ float g_rmax[128u * 512u];
__device__ float g_rsum[128u * 512u];

// =============================================================================
// Kernel 1: 3x3 conv, all three weights (q,k,v) and all 8 output channels per block.
// Block handles one (n, 32-row band). smem input tile shared by 24 outputs/pixel.
// =============================================================================
__global__ void conv3_kernel(const float* __restrict__ x,
                             const float* __restrict__ wq,
                             const float* __restrict__ wk,
                             const float* __restrict__ wv) {
    __shared__ float s_in[8][34][10];       // ci, rows (band-1..band+32), cols padded
    __shared__ float s_w[3][8][8][9];       // qkv, co, ci, tap

    const int n = blockIdx.x;               // 0..1023   (n = b*512 + l)
    const int band = blockIdx.y;            // 0..7
    const int b = n >> 9;
    const int l = n & 511;
    const int tid = threadIdx.x;            // 256 threads

    // weights -> smem (source layout == smem layout)
    for (int e = tid; e < 3 * 576; e += 256) {
        const int q3 = e / 576;
        const int r = e % 576;
        const float* ws = (q3 == 0) ? wq : (q3 == 1) ? wk : wv;
        ((float*)s_w)[e] = ws[r];
    }
    // input tile -> smem (zero-padded)
    for (int e = tid; e < 8 * 34 * 10; e += 256) {
        const int ci = e / 340;
        const int r = e % 340;
        const int yl = r / 10;
        const int xx = r % 10;
        const int gy = band * 32 + yl - 1;
        const int gx = xx - 1;
        float v = 0.f;
        if (gy >= 0 && gy < 256 && gx >= 0 && gx < 8)
            v = x[((((size_t)(b * 8 + ci) * 512 + l) * 256 + gy) * 8) + gx];
        s_in[ci][yl][xx] = v;
    }
    __syncthreads();

    const int j = tid & 7;        // output col 0..7
    const int il = tid >> 3;      // local row 0..31

    float acc[24];
#pragma unroll
    for (int i = 0; i < 24; i++) acc[i] = 0.f;

#pragma unroll
    for (int ci = 0; ci < 8; ci++) {
        float v[9];
#pragma unroll
        for (int di = 0; di < 3; di++)
#pragma unroll
            for (int dj = 0; dj < 3; dj++)
                v[di * 3 + dj] = s_in[ci][il + di][j + dj];
#pragma unroll
        for (int q3 = 0; q3 < 3; q3++)
#pragma unroll
            for (int co = 0; co < 8; co++) {
                const float* wp = s_w[q3][co][ci];
                float a = acc[q3 * 8 + co];
#pragma unroll
                for (int t = 0; t < 9; t++) a = fmaf(v[t], wp[t], a);
                acc[q3 * 8 + co] = a;
            }
    }

    const int y = band * 32 + il;
#pragma unroll
    for (int q3 = 0; q3 < 3; q3++)
#pragma unroll
        for (int co = 0; co < 8; co++)
            g_conv[(size_t)q3 * 16777216u + ((size_t)n * 8 + co) * 2048u + (size_t)y * 8 + j] =
                acc[q3 * 8 + co];
}

// =============================================================================
// Kernel 2: per-channel linear for q/k/v.
// C[g, col] = sum_h W[c][g][h] * conv[qkv][n][c][h][w],  col = n*8+w.
// Output written directly into head layout [(b*8+c)*8+nh][l][d] with
// nh = g>>5, d = ((g&31)<<3)|w.
// 64x64x16 tiles, 256 threads, 4x4 per thread.
// =============================================================================
__global__ void mlin_qkv_kernel(const float* __restrict__ wq,
                                const float* __restrict__ wk,
                                const float* __restrict__ wv) {
    __shared__ float As[16][68];
    __shared__ float Bs[16][68];

    const int z = blockIdx.z;          // 0..23
    const int q3 = z >> 3;
    const int c = z & 7;
    const float* W = ((q3 == 0) ? wq : (q3 == 1) ? wk : wv) + (size_t)c * 65536;
    const float* Bsrc = g_conv + (size_t)q3 * 16777216u + (size_t)c * 2048;

    const int g0 = blockIdx.y * 64;
    const int col0 = blockIdx.x * 64;
    const int tid = threadIdx.x;
    const int tx = tid & 15;
    const int ty = tid >> 4;

    float acc[4][4] = {};

    for (int k0 = 0; k0 < 256; k0 += 16) {
#pragma unroll
        for (int it = 0; it < 4; it++) {
            const int e = it * 256 + tid;
            const int k = e & 15;
            const int m = e >> 4;
            As[k][m] = W[(size_t)(g0 + m) * 256 + k0 + k];
        }
#pragma unroll
        for (int it = 0; it < 4; it++) {
            const int e = it * 256 + tid;
            const int col = e & 63;
            const int k = e >> 6;
            const int cg = col0 + col;
            const int n = cg >> 3;
            const int w = cg & 7;
            Bs[k][col] = Bsrc[(size_t)n * 16384 + (size_t)(k0 + k) * 8 + w];
        }
        __syncthreads();
#pragma unroll
        for (int kk = 0; kk < 16; kk++) {
            const float4 av = *(const float4*)&As[kk][ty * 4];
            const float4 bv = *(const float4*)&Bs[kk][tx * 4];
            const float a[4] = {av.x, av.y, av.z, av.w};
            const float bb[4] = {bv.x, bv.y, bv.z, bv.w};
#pragma unroll
            for (int i = 0; i < 4; i++)
#pragma unroll
                for (int jj = 0; jj < 4; jj++)
                    acc[i][jj] = fmaf(a[i], bb[jj], acc[i][jj]);
        }
        __syncthreads();
    }

    float* dst = (q3 == 0) ? g_q : (q3 == 1) ? g_k : g_v;
#pragma unroll
    for (int i = 0; i < 4; i++) {
        const int g = g0 + ty * 4 + i;
        const int nh = g >> 5;
#pragma unroll
        for (int jj = 0; jj < 4; jj++) {
            const int cg = col0 + tx * 4 + jj;
            const int n = cg >> 3;
            const int w = cg & 7;
            const int b = n >> 9;
            const int l = n & 511;
            const int d = ((g & 31) << 3) | w;
            dst[((((size_t)(b * 8 + c) * 8 + nh) * 512 + l) * 256) + d] = acc[i][jj];
        }
    }
}

// =============================================================================
// Kernel 3: RoPE in-place on first 32 dims of q and k.
// one thread per rotation pair. idx bits: i(4) | l(9) | head(7) | tensor(1)
// =============================================================================
__global__ void rope_kernel() {
    const unsigned idx = blockIdx.x * blockDim.x + threadIdx.x;   // < 2^21
    const int i = idx & 15;
    const int l = (idx >> 4) & 511;
    const int h = (idx >> 13) & 127;
    const int t = (idx >> 20) & 1;
    float* p = (t ? g_k : g_q) + (size_t)h * 131072 + (size_t)l * 256 + 2 * i;
    const float inv = powf(10000.f, -(float)i / 16.f);
    const float f = (float)l * inv;
    const float cs = cosf(f);
    const float sn = sinf(f);
    const float x0 = p[0];
    const float x1 = p[1];
    p[0] = x0 * cs - x1 * sn;
    p[1] = x1 * cs + x0 * sn;
}

// =============================================================================
// Kernel 4: S = Q K^T / 16 + prev_qk, written to the qk output region.
// per head GEMM 512x512x256.
// =============================================================================
__global__ void qk_kernel(const float* __restrict__ prev, float* __restrict__ out_qk) {
    __shared__ float As[16][68];
    __shared__ float Bs[16][68];

    const int head = blockIdx.z;
    const float* Q = g_q + (size_t)head * 131072;
    const float* K = g_k + (size_t)head * 131072;
    const int l0 = blockIdx.y * 64;
    const int m0 = blockIdx.x * 64;
    const int tid = threadIdx.x;
    const int tx = tid & 15;
    const int ty = tid >> 4;

    float acc[4][4] = {};

    for (int k0 = 0; k0 < 256; k0 += 16) {
#pragma unroll
        for (int it = 0; it < 4; it++) {
            const int e = it * 256 + tid;
            const int k = e & 15;
            const int m = e >> 4;
            As[k][m] = Q[(size_t)(l0 + m) * 256 + k0 + k];
            Bs[k][m] = K[(size_t)(m0 + m) * 256 + k0 + k];
        }
        __syncthreads();
#pragma unroll
        for (int kk = 0; kk < 16; kk++) {
            const float4 av = *(const float4*)&As[kk][ty * 4];
            const float4 bv = *(const float4*)&Bs[kk][tx * 4];
            const float a[4] = {av.x, av.y, av.z, av.w};
            const float bb[4] = {bv.x, bv.y, bv.z, bv.w};
#pragma unroll
            for (int i = 0; i < 4; i++)
#pragma unroll
                for (int jj = 0; jj < 4; jj++)
                    acc[i][jj] = fmaf(a[i], bb[jj], acc[i][jj]);
        }
        __syncthreads();
    }

#pragma unroll
    for (int i = 0; i < 4; i++) {
        const int l = l0 + ty * 4 + i;
#pragma unroll
        for (int jj = 0; jj < 4; jj++) {
            const int m = m0 + tx * 4 + jj;
            const size_t off = (size_t)head * 262144 + (size_t)l * 512 + m;
            out_qk[off] = acc[i][jj] * 0.0625f + prev[off];
        }
    }
}

// =============================================================================
// Kernel 5: softmax row stats (max, sum-exp) over the 512-wide rows of qk.
// =============================================================================
__global__ void smax_stats_kernel(const float* __restrict__ qk) {
    const int row = blockIdx.x;                       // 0..65535
    const float* p = qk + (size_t)row * 512;
    const int tid = threadIdx.x;                      // 256
    const float v0 = p[tid];
    const float v1 = p[tid + 256];
    __shared__ float red[256];
    red[tid] = fmaxf(v0, v1);
    __syncthreads();
    for (int s = 128; s > 0; s >>= 1) {
        if (tid < s) red[tid] = fmaxf(red[tid], red[tid + s]);
        __syncthreads();
    }
    const float rmax = red[0];
    __syncthreads();
    red[tid] = expf(v0 - rmax) + expf(v1 - rmax);
    __syncthreads();
    for (int s = 128; s > 0; s >>= 1) {
        if (tid < s) red[tid] += red[tid + s];
        __syncthreads();
    }
    if (tid == 0) {
        g_rmax[row] = rmax;
        g_rsum[row] = red[0];
    }
}

// =============================================================================
// Kernel 6: A = softmax(S) @ V.  exp applied at A-tile load; 1/rsum in epilogue.
// Output stored as [(b*8+c)][l][ch][cw] (the layout the output proj consumes).
// per head GEMM 512x256x512.
// =============================================================================
__global__ void pv_kernel(const float* __restrict__ qk) {
    __shared__ float As[16][68];
    __shared__ float Bs[16][68];

    const int head = blockIdx.z;
    const int bc = head >> 3;
    const int nh = head & 7;
    const float* S = qk + (size_t)head * 262144;
    const float* V = g_v + (size_t)head * 131072;
    const float* rmx = g_rmax + head * 512;
    const float* rsm = g_rsum + head * 512;
    const int l0 = blockIdx.y * 64;
    const int d0 = blockIdx.x * 64;
    const int tid = threadIdx.x;
    const int tx = tid & 15;
    const int ty = tid >> 4;

    float acc[4][4] = {};

    for (int k0 = 0; k0 < 512; k0 += 16) {
#pragma unroll
        for (int it = 0; it < 4; it++) {
            const int e = it * 256 + tid;
            const int k = e & 15;
            const int m = e >> 4;
            As[k][m] = expf(S[(size_t)(l0 + m) * 512 + k0 + k] - rmx[l0 + m]);
        }
#pragma unroll
        for (int it = 0; it < 4; it++) {
            const int e = it * 256 + tid;
            const int col = e & 63;
            const int k = e >> 6;
            Bs[k][col] = V[(size_t)(k0 + k) * 256 + d0 + col];
        }
        __syncthreads();
#pragma unroll
        for (int kk = 0; kk < 16; kk++) {
            const float4 av = *(const float4*)&As[kk][ty * 4];
            const float4 bv = *(const float4*)&Bs[kk][tx * 4];
            const float a[4] = {av.x, av.y, av.z, av.w};
            const float bb[4] = {bv.x, bv.y, bv.z, bv.w};
#pragma unroll
            for (int i = 0; i < 4; i++)
#pragma unroll
                for (int jj = 0; jj < 4; jj++)
                    acc[i][jj] = fmaf(a[i], bb[jj], acc[i][jj]);
        }
        __syncthreads();
    }

#pragma unroll
    for (int i = 0; i < 4; i++) {
        const int l = l0 + ty * 4 + i;
        const float inv = 1.f / rsm[l];
#pragma unroll
        for (int jj = 0; jj < 4; jj++) {
            const int d = d0 + tx * 4 + jj;
            const int hfeat = nh * 32 + (d >> 3);     // ch index 0..255
            const int w = d & 7;
            g_a[((size_t)bc * 512 + l) * 2048 + (size_t)hfeat * 8 + w] = acc[i][jj] * inv;
        }
    }
}

// =============================================================================
// Kernel 7: output projection: out[b,c,l,g,w] = sum_h wo[c][g][h] * a[bc][l][h][w]
// =============================================================================
__global__ void mlin_out_kernel(const float* __restrict__ wo, float* __restrict__ out) {
    __shared__ float As[16][68];
    __shared__ float Bs[16][68];

    const int c = blockIdx.z;
    const float* W = wo + (size_t)c * 65536;
    const int g0 = blockIdx.y * 64;
    const int col0 = blockIdx.x * 64;
    const int tid = threadIdx.x;
    const int tx = tid & 15;
    const int ty = tid >> 4;

    float acc[4][4] = {};

    for (int k0 = 0; k0 < 256; k0 += 16) {
#pragma unroll
        for (int it = 0; it < 4; it++) {
            const int e = it * 256 + tid;
            const int k = e & 15;
            const int m = e >> 4;
            As[k][m] = W[(size_t)(g0 + m) * 256 + k0 + k];
        }
#pragma unroll
        for (int it = 0; it < 4; it++) {
            const int e = it * 256 + tid;
            const int col = e & 63;
            const int k = e >> 6;
            const int cg = col0 + col;
            const int n = cg >> 3;
            const int w = cg & 7;
            const int b = n >> 9;
            const int l = n & 511;
            Bs[k][col] = g_a[((size_t)(b * 8 + c) * 512 + l) * 2048 + (size_t)(k0 + k) * 8 + w];
        }
        __syncthreads();
#pragma unroll
        for (int kk = 0; kk < 16; kk++) {
            const float4 av = *(const float4*)&As[kk][ty * 4];
            const float4 bv = *(const float4*)&Bs[kk][tx * 4];
            const float a[4] = {av.x, av.y, av.z, av.w};
            const float bb[4] = {bv.x, bv.y, bv.z, bv.w};
#pragma unroll
            for (int i = 0; i < 4; i++)
#pragma unroll
                for (int jj = 0; jj < 4; jj++)
                    acc[i][jj] = fmaf(a[i], bb[jj], acc[i][jj]);
        }
        __syncthreads();
    }

#pragma unroll
    for (int i = 0; i < 4; i++) {
        const int g = g0 + ty * 4 + i;
#pragma unroll
        for (int jj = 0; jj < 4; jj++) {
            const int cg = col0 + tx * 4 + jj;
            const int n = cg >> 3;
            const int w = cg & 7;
            const int b = n >> 9;
            const int l = n & 511;
            out[(((size_t)(b * 8 + c) * 512 + l) * 256 + g) * 8 + w] = acc[i][jj];
        }
    }
}

// =============================================================================
extern "C" void kernel_launch(void* const* d_in, const int* in_sizes, int n_in,
                              void* d_out, int out_size) {
    const float* x    = (const float*)d_in[0];
    const float* prev = (const float*)d_in[1];
    const float* cqw  = (const float*)d_in[2];
    const float* ckw  = (const float*)d_in[3];
    const float* cvw  = (const float*)d_in[4];
    const float* wq   = (const float*)d_in[5];
    const float* wk   = (const float*)d_in[6];
    const float* wv   = (const float*)d_in[7];
    const float* wo   = (const float*)d_in[8];
    float* out = (float*)d_out;
    float* out_qk = out + QK_OFF;

    conv3_kernel<<<dim3(1024, 8), 256>>>(x, cqw, ckw, cvw);
    mlin_qkv_kernel<<<dim3(128, 4, 24), 256>>>(wq, wk, wv);
    rope_kernel<<<8192, 256>>>();
    qk_kernel<<<dim3(8, 8, 128), 256>>>(prev, out_qk);
    smax_stats_kernel<<<65536, 256>>>(out_qk);
    pv_kernel<<<dim3(4, 8, 128), 256>>>(out_qk);
    mlin_out_kernel<<<dim3(128, 4, 8), 256>>>(wo, out);
}

// round 4
// speedup vs baseline: 2.2719x; 2.2719x over previous
#include <cuda_runtime.h>
#include <math.h>

// x: (2,8,512,256,8), prev_qk: (2,8,8,512,512), conv w: (8,8,3,3), w*: (8,256,256)
// out = out(2,8,512,256,8) ++ qk(2,8,8,512,512)
#define QK_OFF 16777216ull

// ---------------- scratch ----------------
__device__ float g_conv[3u * 1024u * 8u * 256u * 8u];   // [qkv][n][c][h][w]
__device__ float g_q[128u * 512u * 256u];               // [head][l][d]
__device__ float g_k[128u * 512u * 256u];
__device__ float g_v[128u * 512u * 256u];
__device__ float g_p[128u * 512u * 512u];               // normalized probs, tf32 bits
__device__ float g_a[16u * 512u * 2048u];               // [bc][l][h][w]

// ---------------- tf32 mma helpers ----------------
__device__ __forceinline__ unsigned f2tf(float x) {
    unsigned u;
    asm("cvt.rna.tf32.f32 %0, %1;" : "=r"(u) : "f"(x));
    return u;
}
__device__ __forceinline__ void mma8(float c[4], const unsigned a[4], const unsigned b[2]) {
    asm volatile(
        "mma.sync.aligned.m16n8k8.row.col.f32.tf32.tf32.f32 "
        "{%0,%1,%2,%3},{%4,%5,%6,%7},{%8,%9},{%0,%1,%2,%3};"
        : "+f"(c[0]), "+f"(c[1]), "+f"(c[2]), "+f"(c[3])
        : "r"(a[0]), "r"(a[1]), "r"(a[2]), "r"(a[3]), "r"(b[0]), "r"(b[1]));
}
__device__ __forceinline__ float ex2(float x) {
    float r;
    asm("ex2.approx.f32 %0, %1;" : "=f"(r) : "f"(x));
    return r;
}

// =============================================================================
// Kernel 1: 3x3 conv (unchanged)
// =============================================================================
__global__ void conv3_kernel(const float* __restrict__ x,
                             const float* __restrict__ wq,
                             const float* __restrict__ wk,
                             const float* __restrict__ wv) {
    __shared__ float s_in[8][34][10];
    __shared__ float s_w[3][8][8][9];

    const int n = blockIdx.x;
    const int band = blockIdx.y;
    const int b = n >> 9;
    const int l = n & 511;
    const int tid = threadIdx.x;

    for (int e = tid; e < 3 * 576; e += 256) {
        const int q3 = e / 576;
        const int r = e % 576;
        const float* ws = (q3 == 0) ? wq : (q3 == 1) ? wk : wv;
        ((float*)s_w)[e] = ws[r];
    }
    for (int e = tid; e < 8 * 34 * 10; e += 256) {
        const int ci = e / 340;
        const int r = e % 340;
        const int yl = r / 10;
        const int xx = r % 10;
        const int gy = band * 32 + yl - 1;
        const int gx = xx - 1;
        float v = 0.f;
        if (gy >= 0 && gy < 256 && gx >= 0 && gx < 8)
            v = x[((((size_t)(b * 8 + ci) * 512 + l) * 256 + gy) * 8) + gx];
        s_in[ci][yl][xx] = v;
    }
    __syncthreads();

    const int j = tid & 7;
    const int il = tid >> 3;

    float acc[24];
#pragma unroll
    for (int i = 0; i < 24; i++) acc[i] = 0.f;

#pragma unroll
    for (int ci = 0; ci < 8; ci++) {
        float v[9];
#pragma unroll
        for (int di = 0; di < 3; di++)
#pragma unroll
            for (int dj = 0; dj < 3; dj++)
                v[di * 3 + dj] = s_in[ci][il + di][j + dj];
#pragma unroll
        for (int q3 = 0; q3 < 3; q3++)
#pragma unroll
            for (int co = 0; co < 8; co++) {
                const float* wp = s_w[q3][co][ci];
                float a = acc[q3 * 8 + co];
#pragma unroll
                for (int t = 0; t < 9; t++) a = fmaf(v[t], wp[t], a);
                acc[q3 * 8 + co] = a;
            }
    }

    const int y = band * 32 + il;
#pragma unroll
    for (int q3 = 0; q3 < 3; q3++)
#pragma unroll
        for (int co = 0; co < 8; co++)
            g_conv[(size_t)q3 * 16777216u + ((size_t)n * 8 + co) * 2048u + (size_t)y * 8 + j] =
                acc[q3 * 8 + co];
}

// =============================================================================
// Kernel 2: per-channel q/k/v linear, tf32 mma. C[g,col] = W[g,h] * conv[n,h,w].
// Block tile 128x128x32; 8 warps (4 M x 2 N), warp tile 32x64.
// =============================================================================
__global__ void __launch_bounds__(256) mlin_qkv_mma(const float* __restrict__ wq,
                                                    const float* __restrict__ wk,
                                                    const float* __restrict__ wv) {
    __shared__ unsigned As[128][36];   // [g][k]
    __shared__ unsigned Bs[32][136];   // [k][col]

    const int z = blockIdx.z;
    const int q3 = z >> 3;
    const int c = z & 7;
    const float* W = ((q3 == 0) ? wq : (q3 == 1) ? wk : wv) + (size_t)c * 65536;
    const float* Bsrc = g_conv + (size_t)q3 * 16777216u + (size_t)c * 2048;

    const int g0 = blockIdx.y * 128;
    const int col0 = blockIdx.x * 128;
    const int tid = threadIdx.x;
    const int lane = tid & 31;
    const int warp = tid >> 5;
    const int wm = warp >> 1, wn = warp & 1;

    float C[2][8][4] = {};

    for (int k0 = 0; k0 < 256; k0 += 32) {
#pragma unroll
        for (int it = 0; it < 4; it++) {
            const int idx = it * 256 + tid;
            const int row = idx >> 3, f4 = idx & 7;
            const float4 qa = *(const float4*)(W + (size_t)(g0 + row) * 256 + k0 + f4 * 4);
            *(uint4*)&As[row][f4 * 4] =
                make_uint4(f2tf(qa.x), f2tf(qa.y), f2tf(qa.z), f2tf(qa.w));
            // B: col = nl*8 + w
            const int w4 = idx & 1, nl = (idx >> 1) & 15, kb = idx >> 5;
            const float4 bb = *(const float4*)(Bsrc + (size_t)((col0 >> 3) + nl) * 16384 +
                                               (size_t)(k0 + kb) * 8 + w4 * 4);
            *(uint4*)&Bs[kb][nl * 8 + w4 * 4] =
                make_uint4(f2tf(bb.x), f2tf(bb.y), f2tf(bb.z), f2tf(bb.w));
        }
        __syncthreads();
#pragma unroll
        for (int ks = 0; ks < 4; ks++) {
            const int kk = ks * 8 + (lane & 3);
            unsigned a[2][4];
#pragma unroll
            for (int mi = 0; mi < 2; mi++) {
                const int r = wm * 32 + mi * 16 + (lane >> 2);
                a[mi][0] = As[r][kk];     a[mi][1] = As[r + 8][kk];
                a[mi][2] = As[r][kk + 4]; a[mi][3] = As[r + 8][kk + 4];
            }
            unsigned b[8][2];
#pragma unroll
            for (int ni = 0; ni < 8; ni++) {
                const int n = wn * 64 + ni * 8 + (lane >> 2);
                b[ni][0] = Bs[kk][n];
                b[ni][1] = Bs[kk + 4][n];
            }
#pragma unroll
            for (int mi = 0; mi < 2; mi++)
#pragma unroll
                for (int ni = 0; ni < 8; ni++) mma8(C[mi][ni], a[mi], b[ni]);
        }
        __syncthreads();
    }

    float* dst = (q3 == 0) ? g_q : (q3 == 1) ? g_k : g_v;
#pragma unroll
    for (int mi = 0; mi < 2; mi++) {
        const int gr = g0 + wm * 32 + mi * 16 + (lane >> 2);
#pragma unroll
        for (int ni = 0; ni < 8; ni++) {
            const int cc = col0 + wn * 64 + ni * 8 + (lane & 3) * 2;
#pragma unroll
            for (int e = 0; e < 4; e++) {
                const int g = gr + (e >> 1) * 8;
                const int cg = cc + (e & 1);
                const int nh = g >> 5;
                const int n = cg >> 3, w = cg & 7;
                const int b = n >> 9, l = n & 511;
                const int d = ((g & 31) << 3) | w;
                dst[((((size_t)(b * 8 + c) * 8 + nh) * 512 + l) * 256) + d] = C[mi][ni][e];
            }
        }
    }
}

// =============================================================================
// Kernel 3: RoPE (unchanged)
// =============================================================================
__global__ void rope_kernel() {
    const unsigned idx = blockIdx.x * blockDim.x + threadIdx.x;
    const int i = idx & 15;
    const int l = (idx >> 4) & 511;
    const int h = (idx >> 13) & 127;
    const int t = (idx >> 20) & 1;
    float* p = (t ? g_k : g_q) + (size_t)h * 131072 + (size_t)l * 256 + 2 * i;
    const float inv = powf(10000.f, -(float)i / 16.f);
    const float f = (float)l * inv;
    const float cs = cosf(f);
    const float sn = sinf(f);
    const float x0 = p[0];
    const float x1 = p[1];
    p[0] = x0 * cs - x1 * sn;
    p[1] = x1 * cs + x0 * sn;
}

// =============================================================================
// Kernel 4: S = Q K^T / 16 + prev, tf32 mma. Per head 512x512x256.
// Both A and B tiles stored [row][k] (k contiguous in gmem).
// =============================================================================
__global__ void __launch_bounds__(256) qk_mma(const float* __restrict__ prev,
                                              float* __restrict__ out_qk) {
    __shared__ unsigned As[128][36];
    __shared__ unsigned Bs[128][36];

    const int head = blockIdx.z;
    const float* Q = g_q + (size_t)head * 131072;
    const float* K = g_k + (size_t)head * 131072;
    const int l0 = blockIdx.y * 128;
    const int m0 = blockIdx.x * 128;
    const int tid = threadIdx.x;
    const int lane = tid & 31;
    const int warp = tid >> 5;
    const int wm = warp >> 1, wn = warp & 1;

    float C[2][8][4] = {};

    for (int k0 = 0; k0 < 256; k0 += 32) {
#pragma unroll
        for (int it = 0; it < 4; it++) {
            const int idx = it * 256 + tid;
            const int row = idx >> 3, f4 = idx & 7;
            const float4 qa = *(const float4*)(Q + (size_t)(l0 + row) * 256 + k0 + f4 * 4);
            *(uint4*)&As[row][f4 * 4] =
                make_uint4(f2tf(qa.x), f2tf(qa.y), f2tf(qa.z), f2tf(qa.w));
            const float4 kb = *(const float4*)(K + (size_t)(m0 + row) * 256 + k0 + f4 * 4);
            *(uint4*)&Bs[row][f4 * 4] =
                make_uint4(f2tf(kb.x), f2tf(kb.y), f2tf(kb.z), f2tf(kb.w));
        }
        __syncthreads();
#pragma unroll
        for (int ks = 0; ks < 4; ks++) {
            const int kk = ks * 8 + (lane & 3);
            unsigned a[2][4];
#pragma unroll
            for (int mi = 0; mi < 2; mi++) {
                const int r = wm * 32 + mi * 16 + (lane >> 2);
                a[mi][0] = As[r][kk];     a[mi][1] = As[r + 8][kk];
                a[mi][2] = As[r][kk + 4]; a[mi][3] = As[r + 8][kk + 4];
            }
            unsigned b[8][2];
#pragma unroll
            for (int ni = 0; ni < 8; ni++) {
                const int n = wn * 64 + ni * 8 + (lane >> 2);
                b[ni][0] = Bs[n][kk];
                b[ni][1] = Bs[n][kk + 4];
            }
#pragma unroll
            for (int mi = 0; mi < 2; mi++)
#pragma unroll
                for (int ni = 0; ni < 8; ni++) mma8(C[mi][ni], a[mi], b[ni]);
        }
        __syncthreads();
    }

    const size_t hb = (size_t)head * 262144;
#pragma unroll
    for (int mi = 0; mi < 2; mi++) {
        const int r0 = l0 + wm * 32 + mi * 16 + (lane >> 2);
#pragma unroll
        for (int ni = 0; ni < 8; ni++) {
            const int c0 = m0 + wn * 64 + ni * 8 + (lane & 3) * 2;
            const size_t o0 = hb + (size_t)r0 * 512 + c0;
            const size_t o1 = hb + (size_t)(r0 + 8) * 512 + c0;
            out_qk[o0]     = C[mi][ni][0] * 0.0625f + prev[o0];
            out_qk[o0 + 1] = C[mi][ni][1] * 0.0625f + prev[o0 + 1];
            out_qk[o1]     = C[mi][ni][2] * 0.0625f + prev[o1];
            out_qk[o1 + 1] = C[mi][ni][3] * 0.0625f + prev[o1 + 1];
        }
    }
}

// =============================================================================
// Kernel 5: fused softmax -> normalized P (tf32 bits), ONE exp per element.
// One warp per 512-wide row; 16 elems/thread.
// =============================================================================
__global__ void softmax_kernel(const float* __restrict__ qk) {
    const int row = blockIdx.x * 8 + (threadIdx.x >> 5);
    const int lane = threadIdx.x & 31;
    const float4* p4 = (const float4*)(qk + (size_t)row * 512);

    float4 v[4];
#pragma unroll
    for (int i = 0; i < 4; i++) v[i] = p4[lane + 32 * i];

    float m = -1e30f;
#pragma unroll
    for (int i = 0; i < 4; i++) {
        m = fmaxf(m, fmaxf(fmaxf(v[i].x, v[i].y), fmaxf(v[i].z, v[i].w)));
    }
#pragma unroll
    for (int s = 16; s > 0; s >>= 1) m = fmaxf(m, __shfl_xor_sync(0xFFFFFFFFu, m, s));

    const float L2E = 1.44269504088896f;
    float e[16];
    float sum = 0.f;
#pragma unroll
    for (int i = 0; i < 4; i++) {
        e[i * 4 + 0] = ex2((v[i].x - m) * L2E);
        e[i * 4 + 1] = ex2((v[i].y - m) * L2E);
        e[i * 4 + 2] = ex2((v[i].z - m) * L2E);
        e[i * 4 + 3] = ex2((v[i].w - m) * L2E);
        sum += e[i * 4 + 0] + e[i * 4 + 1] + e[i * 4 + 2] + e[i * 4 + 3];
    }
#pragma unroll
    for (int s = 16; s > 0; s >>= 1) sum += __shfl_xor_sync(0xFFFFFFFFu, sum, s);
    const float inv = 1.f / sum;

    uint4* q4 = (uint4*)(g_p + (size_t)row * 512);
#pragma unroll
    for (int i = 0; i < 4; i++) {
        q4[lane + 32 * i] = make_uint4(f2tf(e[i * 4 + 0] * inv), f2tf(e[i * 4 + 1] * inv),
                                       f2tf(e[i * 4 + 2] * inv), f2tf(e[i * 4 + 3] * inv));
    }
}

// =============================================================================
// Kernel 6: A = P @ V, tf32 mma. Per head 512x256x512. P already normalized+tf32.
// =============================================================================
__global__ void __launch_bounds__(256) pv_mma() {
    __shared__ unsigned As[128][36];   // [l][k]
    __shared__ unsigned Bs[32][136];   // [k][d]

    const int head = blockIdx.z;
    const int bc = head >> 3;
    const int nh = head & 7;
    const float* P = g_p + (size_t)head * 262144;
    const float* V = g_v + (size_t)head * 131072;
    const int l0 = blockIdx.y * 128;
    const int d0 = blockIdx.x * 128;
    const int tid = threadIdx.x;
    const int lane = tid & 31;
    const int warp = tid >> 5;
    const int wm = warp >> 1, wn = warp & 1;

    float C[2][8][4] = {};

    for (int k0 = 0; k0 < 512; k0 += 32) {
#pragma unroll
        for (int it = 0; it < 4; it++) {
            const int idx = it * 256 + tid;
            const int row = idx >> 3, f4 = idx & 7;
            // P is pre-converted tf32 bits: raw copy
            *(uint4*)&As[row][f4 * 4] =
                *(const uint4*)(P + (size_t)(l0 + row) * 512 + k0 + f4 * 4);
            const int n4 = idx & 31, kb = idx >> 5;
            const float4 vb = *(const float4*)(V + (size_t)(k0 + kb) * 256 + d0 + n4 * 4);
            *(uint4*)&Bs[kb][n4 * 4] =
                make_uint4(f2tf(vb.x), f2tf(vb.y), f2tf(vb.z), f2tf(vb.w));
        }
        __syncthreads();
#pragma unroll
        for (int ks = 0; ks < 4; ks++) {
            const int kk = ks * 8 + (lane & 3);
            unsigned a[2][4];
#pragma unroll
            for (int mi = 0; mi < 2; mi++) {
                const int r = wm * 32 + mi * 16 + (lane >> 2);
                a[mi][0] = As[r][kk];     a[mi][1] = As[r + 8][kk];
                a[mi][2] = As[r][kk + 4]; a[mi][3] = As[r + 8][kk + 4];
            }
            unsigned b[8][2];
#pragma unroll
            for (int ni = 0; ni < 8; ni++) {
                const int n = wn * 64 + ni * 8 + (lane >> 2);
                b[ni][0] = Bs[kk][n];
                b[ni][1] = Bs[kk + 4][n];
            }
#pragma unroll
            for (int mi = 0; mi < 2; mi++)
#pragma unroll
                for (int ni = 0; ni < 8; ni++) mma8(C[mi][ni], a[mi], b[ni]);
        }
        __syncthreads();
    }

#pragma unroll
    for (int mi = 0; mi < 2; mi++) {
        const int r0 = l0 + wm * 32 + mi * 16 + (lane >> 2);
#pragma unroll
        for (int ni = 0; ni < 8; ni++) {
            const int c0 = d0 + wn * 64 + ni * 8 + (lane & 3) * 2;
#pragma unroll
            for (int e = 0; e < 4; e++) {
                const int l = r0 + (e >> 1) * 8;
                const int d = c0 + (e & 1);
                const int hfeat = nh * 32 + (d >> 3);
                const int w = d & 7;
                g_a[((size_t)bc * 512 + l) * 2048 + (size_t)hfeat * 8 + w] = C[mi][ni][e];
            }
        }
    }
}

// =============================================================================
// Kernel 7: output projection, tf32 mma. out[b,c,l,g,w] = wo[c][g][h] * a[bc][l][h][w]
// =============================================================================
__global__ void __launch_bounds__(256) mlin_out_mma(const float* __restrict__ wo,
                                                    float* __restrict__ out) {
    __shared__ unsigned As[128][36];
    __shared__ unsigned Bs[32][136];

    const int c = blockIdx.z;
    const float* W = wo + (size_t)c * 65536;
    const int g0 = blockIdx.y * 128;
    const int col0 = blockIdx.x * 128;
    const int tid = threadIdx.x;
    const int lane = tid & 31;
    const int warp = tid >> 5;
    const int wm = warp >> 1, wn = warp & 1;

    float C[2][8][4] = {};

    for (int k0 = 0; k0 < 256; k0 += 32) {
#pragma unroll
        for (int it = 0; it < 4; it++) {
            const int idx = it * 256 + tid;
            const int row = idx >> 3, f4 = idx & 7;
            const float4 qa = *(const float4*)(W + (size_t)(g0 + row) * 256 + k0 + f4 * 4);
            *(uint4*)&As[row][f4 * 4] =
                make_uint4(f2tf(qa.x), f2tf(qa.y), f2tf(qa.z), f2tf(qa.w));
            const int w4 = idx & 1, nl = (idx >> 1) & 15, kb = idx >> 5;
            const int ng = (col0 >> 3) + nl;   // n = b*512 + l
            const int b = ng >> 9, l = ng & 511;
            const float4 bb = *(const float4*)(g_a + ((size_t)(b * 8 + c) * 512 + l) * 2048 +
                                               (size_t)(k0 + kb) * 8 + w4 * 4);
            *(uint4*)&Bs[kb][nl * 8 + w4 * 4] =
                make_uint4(f2tf(bb.x), f2tf(bb.y), f2tf(bb.z), f2tf(bb.w));
        }
        __syncthreads();
#pragma unroll
        for (int ks = 0; ks < 4; ks++) {
            const int kk = ks * 8 + (lane & 3);
            unsigned a[2][4];
#pragma unroll
            for (int mi = 0; mi < 2; mi++) {
                const int r = wm * 32 + mi * 16 + (lane >> 2);
                a[mi][0] = As[r][kk];     a[mi][1] = As[r + 8][kk];
                a[mi][2] = As[r][kk + 4]; a[mi][3] = As[r + 8][kk + 4];
            }
            unsigned b[8][2];
#pragma unroll
            for (int ni = 0; ni < 8; ni++) {
                const int n = wn * 64 + ni * 8 + (lane >> 2);
                b[ni][0] = Bs[kk][n];
                b[ni][1] = Bs[kk + 4][n];
            }
#pragma unroll
            for (int mi = 0; mi < 2; mi++)
#pragma unroll
                for (int ni = 0; ni < 8; ni++) mma8(C[mi][ni], a[mi], b[ni]);
        }
        __syncthreads();
    }

#pragma unroll
    for (int mi = 0; mi < 2; mi++) {
        const int gr = g0 + wm * 32 + mi * 16 + (lane >> 2);
#pragma unroll
        for (int ni = 0; ni < 8; ni++) {
            const int cc = col0 + wn * 64 + ni * 8 + (lane & 3) * 2;
#pragma unroll
            for (int e = 0; e < 4; e++) {
                const int g = gr + (e >> 1) * 8;
                const int cg = cc + (e & 1);
                const int n = cg >> 3, w = cg & 7;
                const int b = n >> 9, l = n & 511;
                out[(((size_t)(b * 8 + c) * 512 + l) * 256 + g) * 8 + w] = C[mi][ni][e];
            }
        }
    }
}

// =============================================================================
extern "C" void kernel_launch(void* const* d_in, const int* in_sizes, int n_in,
                              void* d_out, int out_size) {
    const float* x    = (const float*)d_in[0];
    const float* prev = (const float*)d_in[1];
    const float* cqw  = (const float*)d_in[2];
    const float* ckw  = (const float*)d_in[3];
    const float* cvw  = (const float*)d_in[4];
    const float* wq   = (const float*)d_in[5];
    const float* wk   = (const float*)d_in[6];
    const float* wv   = (const float*)d_in[7];
    const float* wo   = (const float*)d_in[8];
    float* out = (float*)d_out;
    float* out_qk = out + QK_OFF;

    conv3_kernel<<<dim3(1024, 8), 256>>>(x, cqw, ckw, cvw);
    mlin_qkv_mma<<<dim3(64, 2, 24), 256>>>(wq, wk, wv);
    rope_kernel<<<8192, 256>>>();
    qk_mma<<<dim3(4, 4, 128), 256>>>(prev, out_qk);
    softmax_kernel<<<8192, 256>>>(out_qk);
    pv_mma<<<dim3(2, 4, 128), 256>>>();
    mlin_out_mma<<<dim3(64, 2, 8), 256>>>(wo, out);
}

// round 7
// speedup vs baseline: 2.5293x; 1.1133x over previous
#include <cuda_runtime.h>
#include <math.h>

// x: (2,8,512,256,8), prev_qk: (2,8,8,512,512), conv w: (8,8,3,3), w*: (8,256,256)
// out = out(2,8,512,256,8) ++ qk(2,8,8,512,512)
#define QK_OFF 16777216ull

// ---------------- scratch (tf32 bit patterns stored as float) ----------------
__device__ float g_conv[3u * 1024u * 8u * 256u * 8u];   // [qkv][n][c][h][w] (tf32)
__device__ float g_q[128u * 512u * 256u];               // [head][l][d] (tf32)
__device__ float g_k[128u * 512u * 256u];
__device__ float g_v[128u * 512u * 256u];
__device__ float g_p[128u * 512u * 512u];               // normalized probs (tf32)
__device__ float g_a[16u * 512u * 2048u];               // [bc][l][h][w] (tf32)
__device__ float g_wt[4u * 8u * 256u * 256u];           // weights (tf32): wq,wk,wv,wo

// ---------------- helpers ----------------
__device__ __forceinline__ unsigned f2tf(float x) {
    unsigned u;
    asm("cvt.rna.tf32.f32 %0, %1;" : "=r"(u) : "f"(x));
    return u;
}
__device__ __forceinline__ float tfbits(float x) { return __uint_as_float(f2tf(x)); }
__device__ __forceinline__ void mma8(float c[4], const unsigned a[4], const unsigned b[2]) {
    asm volatile(
        "mma.sync.aligned.m16n8k8.row.col.f32.tf32.tf32.f32 "
        "{%0,%1,%2,%3},{%4,%5,%6,%7},{%8,%9},{%0,%1,%2,%3};"
        : "+f"(c[0]), "+f"(c[1]), "+f"(c[2]), "+f"(c[3])
        : "r"(a[0]), "r"(a[1]), "r"(a[2]), "r"(a[3]), "r"(b[0]), "r"(b[1]));
}
__device__ __forceinline__ float ex2(float x) {
    float r;
    asm("ex2.approx.f32 %0, %1;" : "=f"(r) : "f"(x));
    return r;
}
__device__ __forceinline__ void cp16(void* dst, const void* src) {
    unsigned d = (unsigned)__cvta_generic_to_shared(dst);
    asm volatile("cp.async.cg.shared.global [%0], [%1], 16;" :: "r"(d), "l"(src));
}
#define CP_COMMIT asm volatile("cp.async.commit_group;")
#define CP_WAIT1 asm volatile("cp.async.wait_group 1;")
#define CP_WAIT0 asm volatile("cp.async.wait_group 0;")

// smem bytes: stage = A(128x36) + B, two stages
#define QK_SMEM (2 * (128 * 36 + 256 * 36) * 4)   // 110592
#define PV_SMEM (2 * (128 * 36 + 32 * 264) * 4)   // 104448

// =============================================================================
// Kernel 1: 3x3 conv -> g_conv (tf32 bits)
// =============================================================================
__global__ void conv3_kernel(const float* __restrict__ x,
                             const float* __restrict__ wq,
                             const float* __restrict__ wk,
                             const float* __restrict__ wv) {
    __shared__ float s_in[8][34][10];
    __shared__ float s_w[3][8][8][9];

    const int n = blockIdx.x;
    const int band = blockIdx.y;
    const int b = n >> 9;
    const int l = n & 511;
    const int tid = threadIdx.x;

    for (int e = tid; e < 3 * 576; e += 256) {
        const int q3 = e / 576;
        const int r = e % 576;
        const float* ws = (q3 == 0) ? wq : (q3 == 1) ? wk : wv;
        ((float*)s_w)[e] = ws[r];
    }
    for (int e = tid; e < 8 * 34 * 10; e += 256) {
        const int ci = e / 340;
        const int r = e % 340;
        const int yl = r / 10;
        const int xx = r % 10;
        const int gy = band * 32 + yl - 1;
        const int gx = xx - 1;
        float v = 0.f;
        if (gy >= 0 && gy < 256 && gx >= 0 && gx < 8)
            v = x[((((size_t)(b * 8 + ci) * 512 + l) * 256 + gy) * 8) + gx];
        s_in[ci][yl][xx] = v;
    }
    __syncthreads();

    const int j = tid & 7;
    const int il = tid >> 3;

    float acc[24];
#pragma unroll
    for (int i = 0; i < 24; i++) acc[i] = 0.f;

#pragma unroll
    for (int ci = 0; ci < 8; ci++) {
        float v[9];
#pragma unroll
        for (int di = 0; di < 3; di++)
#pragma unroll
            for (int dj = 0; dj < 3; dj++)
                v[di * 3 + dj] = s_in[ci][il + di][j + dj];
#pragma unroll
        for (int q3 = 0; q3 < 3; q3++)
#pragma unroll
            for (int co = 0; co < 8; co++) {
                const float* wp = s_w[q3][co][ci];
                float a = acc[q3 * 8 + co];
#pragma unroll
                for (int t = 0; t < 9; t++) a = fmaf(v[t], wp[t], a);
                acc[q3 * 8 + co] = a;
            }
    }

    const int y = band * 32 + il;
#pragma unroll
    for (int q3 = 0; q3 < 3; q3++)
#pragma unroll
        for (int co = 0; co < 8; co++)
            g_conv[(size_t)q3 * 16777216u + ((size_t)n * 8 + co) * 2048u + (size_t)y * 8 + j] =
                tfbits(acc[q3 * 8 + co]);
}

// =============================================================================
// Kernel 1b: convert all weights to tf32 bits in g_wt
// =============================================================================
__global__ void wcvt_kernel(const float* __restrict__ wq, const float* __restrict__ wk,
                            const float* __restrict__ wv, const float* __restrict__ wo) {
    const int idx = blockIdx.x * 256 + threadIdx.x;      // 0..524287 (float4 units)
    const int t = idx >> 17;                             // 131072 float4 per tensor
    const float* src = (t == 0) ? wq : (t == 1) ? wk : (t == 2) ? wv : wo;
    const float4 v = ((const float4*)src)[idx & 131071];
    ((uint4*)g_wt)[idx] = make_uint4(f2tf(v.x), f2tf(v.y), f2tf(v.z), f2tf(v.w));
}

// =============================================================================
// Common GEMM geometry: block 128(M) x 256(N), k-step 32, 8 warps (2x4),
// warp tile 64x64, m16n8k8 tf32, 2-stage cp.async pipeline.
// =============================================================================

#define GEMM_THREAD_IDS                                   \
    const int tid = threadIdx.x;                          \
    const int lane = tid & 31;                            \
    const int warp = tid >> 5;                            \
    const int wm = warp >> 2, wn = warp & 3;

#define FRAG_COMPUTE(ST, B0_EXPR, B1_EXPR)                                        \
    _Pragma("unroll")                                                             \
    for (int ks = 0; ks < 4; ks++) {                                              \
        const int kk = ks * 8 + (lane & 3);                                       \
        unsigned a[4][4];                                                         \
        _Pragma("unroll")                                                         \
        for (int mi = 0; mi < 4; mi++) {                                          \
            const int r = wm * 64 + mi * 16 + (lane >> 2);                        \
            a[mi][0] = As[ST][r][kk];     a[mi][1] = As[ST][r + 8][kk];           \
            a[mi][2] = As[ST][r][kk + 4]; a[mi][3] = As[ST][r + 8][kk + 4];       \
        }                                                                         \
        unsigned bf[8][2];                                                        \
        _Pragma("unroll")                                                         \
        for (int ni = 0; ni < 8; ni++) {                                          \
            const int n = wn * 64 + ni * 8 + (lane >> 2);                         \
            bf[ni][0] = (B0_EXPR);                                                \
            bf[ni][1] = (B1_EXPR);                                                \
        }                                                                         \
        _Pragma("unroll")                                                         \
        for (int mi = 0; mi < 4; mi++)                                            \
            _Pragma("unroll")                                                     \
            for (int ni = 0; ni < 8; ni++) mma8(C[mi][ni], a[mi], bf[ni]);        \
    }

// =============================================================================
// Kernel 2: q/k/v linear. A = g_wt[q3][c] (256x256), B = g_conv (k=h, col=n*8+w)
// =============================================================================
__global__ void __launch_bounds__(256) mlin_qkv_mma() {
    extern __shared__ __align__(16) unsigned dynsmem[];
    unsigned (*As)[128][36] = (unsigned(*)[128][36])dynsmem;
    unsigned (*Bs)[32][264] = (unsigned(*)[32][264])(dynsmem + 2 * 128 * 36);

    const int z = blockIdx.z;
    const int q3 = z >> 3;
    const int c = z & 7;
    const float* W = g_wt + (size_t)q3 * 524288 + (size_t)c * 65536;
    const float* Bsrc = g_conv + (size_t)q3 * 16777216u + (size_t)c * 2048;
    const int g0 = blockIdx.y * 128;
    const int colb = blockIdx.x * 32;    // col0/8 : n-index base
    GEMM_THREAD_IDS

    float C[4][8][4] = {};

#define LOAD_QKV(ST, K0)                                                              \
    {                                                                                 \
        _Pragma("unroll")                                                             \
        for (int i = 0; i < 4; i++) {                                                 \
            const int idx = i * 256 + tid;                                            \
            const int row = idx >> 3, f4 = idx & 7;                                   \
            cp16(&As[ST][row][f4 * 4], W + (size_t)(g0 + row) * 256 + (K0) + f4 * 4); \
        }                                                                             \
        _Pragma("unroll")                                                             \
        for (int i = 0; i < 8; i++) {                                                 \
            const int idx = i * 256 + tid;                                            \
            const int w4 = idx & 1, nl = (idx >> 1) & 31, kb = idx >> 6;              \
            cp16(&Bs[ST][kb][nl * 8 + w4 * 4],                                        \
                 Bsrc + (size_t)(colb + nl) * 16384 + (size_t)((K0) + kb) * 8 + w4 * 4); \
        }                                                                             \
        CP_COMMIT;                                                                    \
    }

    LOAD_QKV(0, 0)
    LOAD_QKV(1, 32)
#pragma unroll 1
    for (int s = 0; s < 8; s++) {
        if (s == 7) { CP_WAIT0; } else { CP_WAIT1; }
        __syncthreads();
        const int st = s & 1;
        FRAG_COMPUTE(st, Bs[st][kk][n], Bs[st][kk + 4][n])
        __syncthreads();
        if (s + 2 < 8) {
            const int k0 = (s + 2) * 32;
            if (st == 0) LOAD_QKV(0, k0) else LOAD_QKV(1, k0)
        }
    }
#undef LOAD_QKV

    float* dst = (q3 == 0) ? g_q : (q3 == 1) ? g_k : g_v;
#pragma unroll
    for (int mi = 0; mi < 4; mi++) {
        const int gr = g0 + wm * 64 + mi * 16 + (lane >> 2);
#pragma unroll
        for (int ni = 0; ni < 8; ni++) {
            const int cc = colb * 8 + wn * 64 + ni * 8 + (lane & 3) * 2;
#pragma unroll
            for (int e = 0; e < 4; e++) {
                const int g = gr + (e >> 1) * 8;
                const int cg = cc + (e & 1);
                const int nh = g >> 5;
                const int n = cg >> 3, w = cg & 7;
                const int b = n >> 9, l = n & 511;
                const int d = ((g & 31) << 3) | w;
                dst[((((size_t)(b * 8 + c) * 8 + nh) * 512 + l) * 256) + d] =
                    tfbits(C[mi][ni][e]);
            }
        }
    }
}

// =============================================================================
// Kernel 3: RoPE (reads tf32-bit floats, writes tf32 bits)
// =============================================================================
__global__ void rope_kernel() {
    const unsigned idx = blockIdx.x * blockDim.x + threadIdx.x;
    const int i = idx & 15;
    const int l = (idx >> 4) & 511;
    const int h = (idx >> 13) & 127;
    const int t = (idx >> 20) & 1;
    float* p = (t ? g_k : g_q) + (size_t)h * 131072 + (size_t)l * 256 + 2 * i;
    const float inv = powf(10000.f, -(float)i / 16.f);
    const float f = (float)l * inv;
    const float cs = cosf(f);
    const float sn = sinf(f);
    const float x0 = p[0];
    const float x1 = p[1];
    p[0] = tfbits(x0 * cs - x1 * sn);
    p[1] = tfbits(x1 * cs + x0 * sn);
}

// =============================================================================
// Kernel 4: S = Q K^T / 16 + prev. A=Q[128xk], B=K rows (256 of them) [row][k].
// =============================================================================
__global__ void __launch_bounds__(256) qk_mma(const float* __restrict__ prev,
                                              float* __restrict__ out_qk) {
    extern __shared__ __align__(16) unsigned dynsmem[];
    unsigned (*As)[128][36] = (unsigned(*)[128][36])dynsmem;
    unsigned (*Bs)[256][36] = (unsigned(*)[256][36])(dynsmem + 2 * 128 * 36);

    const int head = blockIdx.z;
    const float* Q = g_q + (size_t)head * 131072;
    const float* K = g_k + (size_t)head * 131072;
    const int l0 = blockIdx.y * 128;
    const int m0 = blockIdx.x * 256;
    GEMM_THREAD_IDS

    float C[4][8][4] = {};

#define LOAD_QK(ST, K0)                                                               \
    {                                                                                 \
        _Pragma("unroll")                                                             \
        for (int i = 0; i < 4; i++) {                                                 \
            const int idx = i * 256 + tid;                                            \
            const int row = idx >> 3, f4 = idx & 7;                                   \
            cp16(&As[ST][row][f4 * 4], Q + (size_t)(l0 + row) * 256 + (K0) + f4 * 4); \
        }                                                                             \
        _Pragma("unroll")                                                             \
        for (int i = 0; i < 8; i++) {                                                 \
            const int idx = i * 256 + tid;                                            \
            const int row = idx >> 3, f4 = idx & 7;                                   \
            cp16(&Bs[ST][row][f4 * 4], K + (size_t)(m0 + row) * 256 + (K0) + f4 * 4); \
        }                                                                             \
        CP_COMMIT;                                                                    \
    }

    LOAD_QK(0, 0)
    LOAD_QK(1, 32)
#pragma unroll 1
    for (int s = 0; s < 8; s++) {
        if (s == 7) { CP_WAIT0; } else { CP_WAIT1; }
        __syncthreads();
        const int st = s & 1;
        FRAG_COMPUTE(st, Bs[st][n][kk], Bs[st][n][kk + 4])
        __syncthreads();
        if (s + 2 < 8) {
            const int k0 = (s + 2) * 32;
            if (st == 0) LOAD_QK(0, k0) else LOAD_QK(1, k0)
        }
    }
#undef LOAD_QK

    const size_t hb = (size_t)head * 262144;
#pragma unroll
    for (int mi = 0; mi < 4; mi++) {
        const int r0 = l0 + wm * 64 + mi * 16 + (lane >> 2);
#pragma unroll
        for (int ni = 0; ni < 8; ni++) {
            const int c0 = m0 + wn * 64 + ni * 8 + (lane & 3) * 2;
            const size_t o0 = hb + (size_t)r0 * 512 + c0;
            const size_t o1 = hb + (size_t)(r0 + 8) * 512 + c0;
            out_qk[o0]     = C[mi][ni][0] * 0.0625f + prev[o0];
            out_qk[o0 + 1] = C[mi][ni][1] * 0.0625f + prev[o0 + 1];
            out_qk[o1]     = C[mi][ni][2] * 0.0625f + prev[o1];
            out_qk[o1 + 1] = C[mi][ni][3] * 0.0625f + prev[o1 + 1];
        }
    }
}

// =============================================================================
// Kernel 5: softmax -> normalized P (tf32 bits). One warp per 512-row.
// =============================================================================
__global__ void softmax_kernel(const float* __restrict__ qk) {
    const int row = blockIdx.x * 8 + (threadIdx.x >> 5);
    const int lane = threadIdx.x & 31;
    const float4* p4 = (const float4*)(qk + (size_t)row * 512);

    float4 v[4];
#pragma unroll
    for (int i = 0; i < 4; i++) v[i] = p4[lane + 32 * i];

    float m = -1e30f;
#pragma unroll
    for (int i = 0; i < 4; i++)
        m = fmaxf(m, fmaxf(fmaxf(v[i].x, v[i].y), fmaxf(v[i].z, v[i].w)));
#pragma unroll
    for (int s = 16; s > 0; s >>= 1) m = fmaxf(m, __shfl_xor_sync(0xFFFFFFFFu, m, s));

    const float L2E = 1.44269504088896f;
    float e[16];
    float sum = 0.f;
#pragma unroll
    for (int i = 0; i < 4; i++) {
        e[i * 4 + 0] = ex2((v[i].x - m) * L2E);
        e[i * 4 + 1] = ex2((v[i].y - m) * L2E);
        e[i * 4 + 2] = ex2((v[i].z - m) * L2E);
        e[i * 4 + 3] = ex2((v[i].w - m) * L2E);
        sum += e[i * 4 + 0] + e[i * 4 + 1] + e[i * 4 + 2] + e[i * 4 + 3];
    }
#pragma unroll
    for (int s = 16; s > 0; s >>= 1) sum += __shfl_xor_sync(0xFFFFFFFFu, sum, s);
    const float inv = 1.f / sum;

    uint4* q4 = (uint4*)(g_p + (size_t)row * 512);
#pragma unroll
    for (int i = 0; i < 4; i++) {
        q4[lane + 32 * i] = make_uint4(f2tf(e[i * 4 + 0] * inv), f2tf(e[i * 4 + 1] * inv),
                                       f2tf(e[i * 4 + 2] * inv), f2tf(e[i * 4 + 3] * inv));
    }
}

// =============================================================================
// Kernel 6: A = P @ V. A=P[128 x k(512)], B=V [k][d=256].
// =============================================================================
__global__ void __launch_bounds__(256) pv_mma() {
    extern __shared__ __align__(16) unsigned dynsmem[];
    unsigned (*As)[128][36] = (unsigned(*)[128][36])dynsmem;
    unsigned (*Bs)[32][264] = (unsigned(*)[32][264])(dynsmem + 2 * 128 * 36);

    const int head = blockIdx.z;
    const int bc = head >> 3;
    const int nh = head & 7;
    const float* P = g_p + (size_t)head * 262144;
    const float* V = g_v + (size_t)head * 131072;
    const int l0 = blockIdx.y * 128;
    GEMM_THREAD_IDS

    float C[4][8][4] = {};

#define LOAD_PV(ST, K0)                                                               \
    {                                                                                 \
        _Pragma("unroll")                                                             \
        for (int i = 0; i < 4; i++) {                                                 \
            const int idx = i * 256 + tid;                                            \
            const int row = idx >> 3, f4 = idx & 7;                                   \
            cp16(&As[ST][row][f4 * 4], P + (size_t)(l0 + row) * 512 + (K0) + f4 * 4); \
        }                                                                             \
        _Pragma("unroll")                                                             \
        for (int i = 0; i < 8; i++) {                                                 \
            const int idx = i * 256 + tid;                                            \
            const int kb = idx >> 6, n4 = idx & 63;                                   \
            cp16(&Bs[ST][kb][n4 * 4], V + (size_t)((K0) + kb) * 256 + n4 * 4);        \
        }                                                                             \
        CP_COMMIT;                                                                    \
    }

    LOAD_PV(0, 0)
    LOAD_PV(1, 32)
#pragma unroll 1
    for (int s = 0; s < 16; s++) {
        if (s == 15) { CP_WAIT0; } else { CP_WAIT1; }
        __syncthreads();
        const int st = s & 1;
        FRAG_COMPUTE(st, Bs[st][kk][n], Bs[st][kk + 4][n])
        __syncthreads();
        if (s + 2 < 16) {
            const int k0 = (s + 2) * 32;
            if (st == 0) LOAD_PV(0, k0) else LOAD_PV(1, k0)
        }
    }
#undef LOAD_PV

#pragma unroll
    for (int mi = 0; mi < 4; mi++) {
        const int r0 = l0 + wm * 64 + mi * 16 + (lane >> 2);
#pragma unroll
        for (int ni = 0; ni < 8; ni++) {
            const int c0 = wn * 64 + ni * 8 + (lane & 3) * 2;
#pragma unroll
            for (int e = 0; e < 4; e++) {
                const int l = r0 + (e >> 1) * 8;
                const int d = c0 + (e & 1);
                const int hfeat = nh * 32 + (d >> 3);
                const int w = d & 7;
                g_a[((size_t)bc * 512 + l) * 2048 + (size_t)hfeat * 8 + w] =
                    tfbits(C[mi][ni][e]);
            }
        }
    }
}

// =============================================================================
// Kernel 7: output projection. A = g_wt[3][c], B = g_a (k=h, col=n*8+w).
// =============================================================================
__global__ void __launch_bounds__(256) mlin_out_mma(float* __restrict__ out) {
    extern __shared__ __align__(16) unsigned dynsmem[];
    unsigned (*As)[128][36] = (unsigned(*)[128][36])dynsmem;
    unsigned (*Bs)[32][264] = (unsigned(*)[32][264])(dynsmem + 2 * 128 * 36);

    const int c = blockIdx.z;
    const float* W = g_wt + 3u * 524288 + (size_t)c * 65536;
    const int g0 = blockIdx.y * 128;
    const int colb = blockIdx.x * 32;    // n-index base
    GEMM_THREAD_IDS

    float C[4][8][4] = {};

#define LOAD_OUT(ST, K0)                                                              \
    {                                                                                 \
        _Pragma("unroll")                                                             \
        for (int i = 0; i < 4; i++) {                                                 \
            const int idx = i * 256 + tid;                                            \
            const int row = idx >> 3, f4 = idx & 7;                                   \
            cp16(&As[ST][row][f4 * 4], W + (size_t)(g0 + row) * 256 + (K0) + f4 * 4); \
        }                                                                             \
        _Pragma("unroll")                                                             \
        for (int i = 0; i < 8; i++) {                                                 \
            const int idx = i * 256 + tid;                                            \
            const int w4 = idx & 1, nl = (idx >> 1) & 31, kb = idx >> 6;              \
            const int n = colb + nl;                                                  \
            const int b = n >> 9, l = n & 511;                                        \
            cp16(&Bs[ST][kb][nl * 8 + w4 * 4],                                        \
                 g_a + ((size_t)(b * 8 + c) * 512 + l) * 2048 +                       \
                     (size_t)((K0) + kb) * 8 + w4 * 4);                               \
        }                                                                             \
        CP_COMMIT;                                                                    \
    }

    LOAD_OUT(0, 0)
    LOAD_OUT(1, 32)
#pragma unroll 1
    for (int s = 0; s < 8; s++) {
        if (s == 7) { CP_WAIT0; } else { CP_WAIT1; }
        __syncthreads();
        const int st = s & 1;
        FRAG_COMPUTE(st, Bs[st][kk][n], Bs[st][kk + 4][n])
        __syncthreads();
        if (s + 2 < 8) {
            const int k0 = (s + 2) * 32;
            if (st == 0) LOAD_OUT(0, k0) else LOAD_OUT(1, k0)
        }
    }
#undef LOAD_OUT

#pragma unroll
    for (int mi = 0; mi < 4; mi++) {
        const int gr = g0 + wm * 64 + mi * 16 + (lane >> 2);
#pragma unroll
        for (int ni = 0; ni < 8; ni++) {
            const int cc = colb * 8 + wn * 64 + ni * 8 + (lane & 3) * 2;
#pragma unroll
            for (int e = 0; e < 4; e++) {
                const int g = gr + (e >> 1) * 8;
                const int cg = cc + (e & 1);
                const int n = cg >> 3, w = cg & 7;
                const int b = n >> 9, l = n & 511;
                out[(((size_t)(b * 8 + c) * 512 + l) * 256 + g) * 8 + w] = C[mi][ni][e];
            }
        }
    }
}

// =============================================================================
extern "C" void kernel_launch(void* const* d_in, const int* in_sizes, int n_in,
                              void* d_out, int out_size) {
    const float* x    = (const float*)d_in[0];
    const float* prev = (const float*)d_in[1];
    const float* cqw  = (const float*)d_in[2];
    const float* ckw  = (const float*)d_in[3];
    const float* cvw  = (const float*)d_in[4];
    const float* wq   = (const float*)d_in[5];
    const float* wk   = (const float*)d_in[6];
    const float* wv   = (const float*)d_in[7];
    const float* wo   = (const float*)d_in[8];
    float* out = (float*)d_out;
    float* out_qk = out + QK_OFF;

    static bool attr_done = false;
    if (!attr_done) {
        cudaFuncSetAttribute(mlin_qkv_mma, cudaFuncAttributeMaxDynamicSharedMemorySize, PV_SMEM);
        cudaFuncSetAttribute(qk_mma, cudaFuncAttributeMaxDynamicSharedMemorySize, QK_SMEM);
        cudaFuncSetAttribute(pv_mma, cudaFuncAttributeMaxDynamicSharedMemorySize, PV_SMEM);
        cudaFuncSetAttribute(mlin_out_mma, cudaFuncAttributeMaxDynamicSharedMemorySize, PV_SMEM);
        attr_done = true;
    }

    conv3_kernel<<<dim3(1024, 8), 256>>>(x, cqw, ckw, cvw);
    wcvt_kernel<<<2048, 256>>>(wq, wk, wv, wo);
    mlin_qkv_mma<<<dim3(32, 2, 24), 256, PV_SMEM>>>();
    rope_kernel<<<8192, 256>>>();
    qk_mma<<<dim3(2, 4, 128), 256, QK_SMEM>>>(prev, out_qk);
    softmax_kernel<<<8192, 256>>>(out_qk);
    pv_mma<<<dim3(1, 4, 128), 256, PV_SMEM>>>();
    mlin_out_mma<<<dim3(32, 2, 8), 256, PV_SMEM>>>(out);
}

// round 9
// speedup vs baseline: 2.6828x; 1.0607x over previous
#include <cuda_runtime.h>
#include <math.h>

// x: (2,8,512,256,8), prev_qk: (2,8,8,512,512), conv w: (8,8,3,3), w*: (8,256,256)
// out = out(2,8,512,256,8) ++ qk(2,8,8,512,512)
#define QK_OFF 16777216ull

// ---------------- scratch (tf32 bit patterns stored as float) ----------------
__device__ float g_conv[3u * 1024u * 8u * 256u * 8u];   // [qkv][n][c][h][w] (tf32)
__device__ float g_q[128u * 512u * 256u];               // [head][l][d] (tf32)
__device__ float g_k[128u * 512u * 256u];
__device__ float g_v[128u * 512u * 256u];
__device__ float g_p[128u * 512u * 512u];               // normalized probs (tf32)
__device__ float g_a[16u * 512u * 2048u];               // [bc][l][h][w] (tf32)
__device__ float g_wt[4u * 8u * 256u * 256u];           // weights (tf32): wq,wk,wv,wo

// ---------------- helpers ----------------
__device__ __forceinline__ unsigned f2tf(float x) {
    unsigned u;
    asm("cvt.rna.tf32.f32 %0, %1;" : "=r"(u) : "f"(x));
    return u;
}
__device__ __forceinline__ float tfbits(float x) { return __uint_as_float(f2tf(x)); }
__device__ __forceinline__ void mma8(float c[4], const unsigned a[4], const unsigned b[2]) {
    asm volatile(
        "mma.sync.aligned.m16n8k8.row.col.f32.tf32.tf32.f32 "
        "{%0,%1,%2,%3},{%4,%5,%6,%7},{%8,%9},{%0,%1,%2,%3};"
        : "+f"(c[0]), "+f"(c[1]), "+f"(c[2]), "+f"(c[3])
        : "r"(a[0]), "r"(a[1]), "r"(a[2]), "r"(a[3]), "r"(b[0]), "r"(b[1]));
}
__device__ __forceinline__ float ex2(float x) {
    float r;
    asm("ex2.approx.f32 %0, %1;" : "=f"(r) : "f"(x));
    return r;
}
__device__ __forceinline__ void cp16(void* dst, const void* src) {
    unsigned d = (unsigned)__cvta_generic_to_shared(dst);
    asm volatile("cp.async.cg.shared.global [%0], [%1], 16;" :: "r"(d), "l"(src));
}
#define CP_COMMIT asm volatile("cp.async.commit_group;")
#define CP_WAIT1 asm volatile("cp.async.wait_group 1;")
#define CP_WAIT0 asm volatile("cp.async.wait_group 0;")

// 3-stage smem: stage = A(128x36) + B
#define QK_SMEM3 (3 * (128 * 36 + 128 * 36) * 4)    // 110592
#define PV_SMEM3 (3 * (128 * 36 + 32 * 136) * 4)    // 107520

// =============================================================================
// Kernel 1: 3x3 conv -> g_conv (tf32 bits)
// =============================================================================
__global__ void conv3_kernel(const float* __restrict__ x,
                             const float* __restrict__ wq,
                             const float* __restrict__ wk,
                             const float* __restrict__ wv) {
    __shared__ float s_in[8][34][10];
    __shared__ float s_w[3][8][8][9];

    const int n = blockIdx.x;
    const int band = blockIdx.y;
    const int b = n >> 9;
    const int l = n & 511;
    const int tid = threadIdx.x;

    for (int e = tid; e < 3 * 576; e += 256) {
        const int q3 = e / 576;
        const int r = e % 576;
        const float* ws = (q3 == 0) ? wq : (q3 == 1) ? wk : wv;
        ((float*)s_w)[e] = ws[r];
    }
    for (int e = tid; e < 8 * 34 * 10; e += 256) {
        const int ci = e / 340;
        const int r = e % 340;
        const int yl = r / 10;
        const int xx = r % 10;
        const int gy = band * 32 + yl - 1;
        const int gx = xx - 1;
        float v = 0.f;
        if (gy >= 0 && gy < 256 && gx >= 0 && gx < 8)
            v = x[((((size_t)(b * 8 + ci) * 512 + l) * 256 + gy) * 8) + gx];
        s_in[ci][yl][xx] = v;
    }
    __syncthreads();

    const int j = tid & 7;
    const int il = tid >> 3;

    float acc[24];
#pragma unroll
    for (int i = 0; i < 24; i++) acc[i] = 0.f;

#pragma unroll
    for (int ci = 0; ci < 8; ci++) {
        float v[9];
#pragma unroll
        for (int di = 0; di < 3; di++)
#pragma unroll
            for (int dj = 0; dj < 3; dj++)
                v[di * 3 + dj] = s_in[ci][il + di][j + dj];
#pragma unroll
        for (int q3 = 0; q3 < 3; q3++)
#pragma unroll
            for (int co = 0; co < 8; co++) {
                const float* wp = s_w[q3][co][ci];
                float a = acc[q3 * 8 + co];
#pragma unroll
                for (int t = 0; t < 9; t++) a = fmaf(v[t], wp[t], a);
                acc[q3 * 8 + co] = a;
            }
    }

    const int y = band * 32 + il;
#pragma unroll
    for (int q3 = 0; q3 < 3; q3++)
#pragma unroll
        for (int co = 0; co < 8; co++)
            g_conv[(size_t)q3 * 16777216u + ((size_t)n * 8 + co) * 2048u + (size_t)y * 8 + j] =
                tfbits(acc[q3 * 8 + co]);
}

// =============================================================================
// Kernel 1b: convert all weights to tf32 bits in g_wt
// =============================================================================
__global__ void wcvt_kernel(const float* __restrict__ wq, const float* __restrict__ wk,
                            const float* __restrict__ wv, const float* __restrict__ wo) {
    const int idx = blockIdx.x * 256 + threadIdx.x;
    const int t = idx >> 17;
    const float* src = (t == 0) ? wq : (t == 1) ? wk : (t == 2) ? wv : wo;
    const float4 v = ((const float4*)src)[idx & 131071];
    ((uint4*)g_wt)[idx] = make_uint4(f2tf(v.x), f2tf(v.y), f2tf(v.z), f2tf(v.w));
}

// =============================================================================
// GEMM geometry: block 128x128, k-step 32, 3-stage cp.async, ONE sync/iter.
// 8 warps (2 M x 4 N), warp tile 64x32, m16n8k8 tf32.
// =============================================================================

#define GEMM_THREAD_IDS                                   \
    const int tid = threadIdx.x;                          \
    const int lane = tid & 31;                            \
    const int warp = tid >> 5;                            \
    const int wm = warp >> 2, wn = warp & 3;

#define FRAG_COMPUTE(ST, B0_EXPR, B1_EXPR)                                        \
    _Pragma("unroll")                                                             \
    for (int ks = 0; ks < 4; ks++) {                                              \
        const int kk = ks * 8 + (lane & 3);                                       \
        unsigned a[4][4];                                                         \
        _Pragma("unroll")                                                         \
        for (int mi = 0; mi < 4; mi++) {                                          \
            const int r = wm * 64 + mi * 16 + (lane >> 2);                        \
            a[mi][0] = As[ST][r][kk];     a[mi][1] = As[ST][r + 8][kk];           \
            a[mi][2] = As[ST][r][kk + 4]; a[mi][3] = As[ST][r + 8][kk + 4];       \
        }                                                                         \
        unsigned bf[4][2];                                                        \
        _Pragma("unroll")                                                         \
        for (int ni = 0; ni < 4; ni++) {                                          \
            const int n = wn * 32 + ni * 8 + (lane >> 2);                         \
            bf[ni][0] = (B0_EXPR);                                                \
            bf[ni][1] = (B1_EXPR);                                                \
        }                                                                         \
        _Pragma("unroll")                                                         \
        for (int mi = 0; mi < 4; mi++)                                            \
            _Pragma("unroll")                                                     \
            for (int ni = 0; ni < 4; ni++) mma8(C[mi][ni], a[mi], bf[ni]);        \
    }

// pipeline driver: LOADM(stage, k0) must end with CP_COMMIT
#define PIPE_LOOP(KS, LOADM, COMPUTE)                     \
    LOADM(0, 0)                                           \
    LOADM(1, 32)                                          \
    _Pragma("unroll 1")                                   \
    for (int s = 0; s < (KS); s++) {                      \
        if (s + 1 < (KS)) { CP_WAIT1; } else { CP_WAIT0; }\
        __syncthreads();                                  \
        const int st = s % 3;                             \
        COMPUTE                                           \
        if (s + 2 < (KS)) {                               \
            const int ld = (s + 2) % 3;                   \
            const int k0 = (s + 2) * 32;                  \
            LOADM(ld, k0)                                 \
        }                                                 \
    }

// =============================================================================
// Kernel 2: q/k/v linear + fused RoPE. A = g_wt[q3][c], B = g_conv.
// =============================================================================
__global__ void __launch_bounds__(256, 2) mlin_qkv_mma() {
    extern __shared__ __align__(16) unsigned dynsmem[];
    unsigned (*As)[128][36] = (unsigned(*)[128][36])dynsmem;
    unsigned (*Bs)[32][136] = (unsigned(*)[32][136])(dynsmem + 3 * 128 * 36);

    const int z = blockIdx.z;
    const int q3 = z >> 3;
    const int c = z & 7;
    const float* W = g_wt + (size_t)q3 * 524288 + (size_t)c * 65536;
    const float* Bsrc = g_conv + (size_t)q3 * 16777216u + (size_t)c * 2048;
    const int g0 = blockIdx.y * 128;
    const int colb = blockIdx.x * 16;    // n-index base (16 n per block)
    GEMM_THREAD_IDS

    float C[4][4][4] = {};

#define LOAD_QKV(ST, K0)                                                              \
    {                                                                                 \
        _Pragma("unroll")                                                             \
        for (int i = 0; i < 4; i++) {                                                 \
            const int idx = i * 256 + tid;                                            \
            const int row = idx >> 3, f4 = idx & 7;                                   \
            cp16(&As[ST][row][f4 * 4], W + (size_t)(g0 + row) * 256 + (K0) + f4 * 4); \
        }                                                                             \
        _Pragma("unroll")                                                             \
        for (int i = 0; i < 4; i++) {                                                 \
            const int idx = i * 256 + tid;                                            \
            const int w4 = idx & 1, nl = (idx >> 1) & 15, kb = idx >> 5;              \
            cp16(&Bs[ST][kb][nl * 8 + w4 * 4],                                        \
                 Bsrc + (size_t)(colb + nl) * 16384 + (size_t)((K0) + kb) * 8 + w4 * 4); \
        }                                                                             \
        CP_COMMIT;                                                                    \
    }

    PIPE_LOOP(8, LOAD_QKV, FRAG_COMPUTE(st, Bs[st][kk][n], Bs[st][kk + 4][n]))
#undef LOAD_QKV

    float* dst = (q3 == 0) ? g_q : (q3 == 1) ? g_k : g_v;
#pragma unroll
    for (int mi = 0; mi < 4; mi++) {
        const int gr = g0 + wm * 64 + mi * 16 + (lane >> 2);
#pragma unroll
        for (int ni = 0; ni < 4; ni++) {
            const int cc = colb * 8 + wn * 32 + ni * 8 + (lane & 3) * 2;
            const int n = cc >> 3, w0 = cc & 7;
            const int b = n >> 9, l = n & 511;
#pragma unroll
            for (int pr = 0; pr < 2; pr++) {
                const int g = gr + pr * 8;
                float v0 = C[mi][ni][pr * 2];
                float v1 = C[mi][ni][pr * 2 + 1];
                const int d0 = ((g & 31) << 3) | w0;
                if (q3 < 2 && d0 < 32) {       // fused RoPE on first 32 dims of q,k
                    const int ri = d0 >> 1;
                    const float inv = powf(10000.f, -(float)ri / 16.f);
                    const float f = (float)l * inv;
                    const float cs = cosf(f), sn = sinf(f);
                    const float r0 = v0 * cs - v1 * sn;
                    const float r1 = v1 * cs + v0 * sn;
                    v0 = r0; v1 = r1;
                }
                const int nh = g >> 5;
                const size_t base =
                    ((((size_t)(b * 8 + c) * 8 + nh) * 512 + l) * 256) + d0;
                dst[base]     = tfbits(v0);
                dst[base + 1] = tfbits(v1);
            }
        }
    }
}

// =============================================================================
// Kernel 4: S = Q K^T / 16 + prev. B tile = 128 K-rows, [row][k] layout.
// =============================================================================
__global__ void __launch_bounds__(256, 2) qk_mma(const float* __restrict__ prev,
                                                 float* __restrict__ out_qk) {
    extern __shared__ __align__(16) unsigned dynsmem[];
    unsigned (*As)[128][36] = (unsigned(*)[128][36])dynsmem;
    unsigned (*Bs)[128][36] = (unsigned(*)[128][36])(dynsmem + 3 * 128 * 36);

    const int head = blockIdx.z;
    const float* Q = g_q + (size_t)head * 131072;
    const float* K = g_k + (size_t)head * 131072;
    const int l0 = blockIdx.y * 128;
    const int m0 = blockIdx.x * 128;
    GEMM_THREAD_IDS

    float C[4][4][4] = {};

#define LOAD_QK(ST, K0)                                                               \
    {                                                                                 \
        _Pragma("unroll")                                                             \
        for (int i = 0; i < 4; i++) {                                                 \
            const int idx = i * 256 + tid;                                            \
            const int row = idx >> 3, f4 = idx & 7;                                   \
            cp16(&As[ST][row][f4 * 4], Q + (size_t)(l0 + row) * 256 + (K0) + f4 * 4); \
            cp16(&Bs[ST][row][f4 * 4], K + (size_t)(m0 + row) * 256 + (K0) + f4 * 4); \
        }                                                                             \
        CP_COMMIT;                                                                    \
    }

    PIPE_LOOP(8, LOAD_QK, FRAG_COMPUTE(st, Bs[st][n][kk], Bs[st][n][kk + 4]))
#undef LOAD_QK

    const size_t hb = (size_t)head * 262144;
#pragma unroll
    for (int mi = 0; mi < 4; mi++) {
        const int r0 = l0 + wm * 64 + mi * 16 + (lane >> 2);
#pragma unroll
        for (int ni = 0; ni < 4; ni++) {
            const int c0 = m0 + wn * 32 + ni * 8 + (lane & 3) * 2;
            const size_t o0 = hb + (size_t)r0 * 512 + c0;
            const size_t o1 = hb + (size_t)(r0 + 8) * 512 + c0;
            out_qk[o0]     = C[mi][ni][0] * 0.0625f + prev[o0];
            out_qk[o0 + 1] = C[mi][ni][1] * 0.0625f + prev[o0 + 1];
            out_qk[o1]     = C[mi][ni][2] * 0.0625f + prev[o1];
            out_qk[o1 + 1] = C[mi][ni][3] * 0.0625f + prev[o1 + 1];
        }
    }
}

// =============================================================================
// Kernel 5: softmax -> normalized P (tf32 bits). One warp per 512-row.
// =============================================================================
__global__ void softmax_kernel(const float* __restrict__ qk) {
    const int row = blockIdx.x * 8 + (threadIdx.x >> 5);
    const int lane = threadIdx.x & 31;
    const float4* p4 = (const float4*)(qk + (size_t)row * 512);

    float4 v[4];
#pragma unroll
    for (int i = 0; i < 4; i++) v[i] = p4[lane + 32 * i];

    float m = -1e30f;
#pragma unroll
    for (int i = 0; i < 4; i++)
        m = fmaxf(m, fmaxf(fmaxf(v[i].x, v[i].y), fmaxf(v[i].z, v[i].w)));
#pragma unroll
    for (int s = 16; s > 0; s >>= 1) m = fmaxf(m, __shfl_xor_sync(0xFFFFFFFFu, m, s));

    const float L2E = 1.44269504088896f;
    float e[16];
    float sum = 0.f;
#pragma unroll
    for (int i = 0; i < 4; i++) {
        e[i * 4 + 0] = ex2((v[i].x - m) * L2E);
        e[i * 4 + 1] = ex2((v[i].y - m) * L2E);
        e[i * 4 + 2] = ex2((v[i].z - m) * L2E);
        e[i * 4 + 3] = ex2((v[i].w - m) * L2E);
        sum += e[i * 4 + 0] + e[i * 4 + 1] + e[i * 4 + 2] + e[i * 4 + 3];
    }
#pragma unroll
    for (int s = 16; s > 0; s >>= 1) sum += __shfl_xor_sync(0xFFFFFFFFu, sum, s);
    const float inv = 1.f / sum;

    uint4* q4 = (uint4*)(g_p + (size_t)row * 512);
#pragma unroll
    for (int i = 0; i < 4; i++) {
        q4[lane + 32 * i] = make_uint4(f2tf(e[i * 4 + 0] * inv), f2tf(e[i * 4 + 1] * inv),
                                       f2tf(e[i * 4 + 2] * inv), f2tf(e[i * 4 + 3] * inv));
    }
}

// =============================================================================
// Kernel 6: A = P @ V.
// =============================================================================
__global__ void __launch_bounds__(256, 2) pv_mma() {
    extern __shared__ __align__(16) unsigned dynsmem[];
    unsigned (*As)[128][36] = (unsigned(*)[128][36])dynsmem;
    unsigned (*Bs)[32][136] = (unsigned(*)[32][136])(dynsmem + 3 * 128 * 36);

    const int head = blockIdx.z;
    const int bc = head >> 3;
    const int nh = head & 7;
    const float* P = g_p + (size_t)head * 262144;
    const float* V = g_v + (size_t)head * 131072;
    const int l0 = blockIdx.y * 128;
    const int d0b = blockIdx.x * 128;
    GEMM_THREAD_IDS

    float C[4][4][4] = {};

#define LOAD_PV(ST, K0)                                                               \
    {                                                                                 \
        _Pragma("unroll")                                                             \
        for (int i = 0; i < 4; i++) {                                                 \
            const int idx = i * 256 + tid;                                            \
            const int row = idx >> 3, f4 = idx & 7;                                   \
            cp16(&As[ST][row][f4 * 4], P + (size_t)(l0 + row) * 512 + (K0) + f4 * 4); \
        }                                                                             \
        _Pragma("unroll")                                                             \
        for (int i = 0; i < 4; i++) {                                                 \
            const int idx = i * 256 + tid;                                            \
            const int kb = idx >> 5, n4 = idx & 31;                                   \
            cp16(&Bs[ST][kb][n4 * 4], V + (size_t)((K0) + kb) * 256 + d0b + n4 * 4);  \
        }                                                                             \
        CP_COMMIT;                                                                    \
    }

    PIPE_LOOP(16, LOAD_PV, FRAG_COMPUTE(st, Bs[st][kk][n], Bs[st][kk + 4][n]))
#undef LOAD_PV

#pragma unroll
    for (int mi = 0; mi < 4; mi++) {
        const int r0 = l0 + wm * 64 + mi * 16 + (lane >> 2);
#pragma unroll
        for (int ni = 0; ni < 4; ni++) {
            const int c0 = d0b + wn * 32 + ni * 8 + (lane & 3) * 2;
#pragma unroll
            for (int e = 0; e < 4; e++) {
                const int l = r0 + (e >> 1) * 8;
                const int d = c0 + (e & 1);
                const int hfeat = nh * 32 + (d >> 3);
                const int w = d & 7;
                g_a[((size_t)bc * 512 + l) * 2048 + (size_t)hfeat * 8 + w] =
                    tfbits(C[mi][ni][e]);
            }
        }
    }
}

// =============================================================================
// Kernel 7: output projection.
// =============================================================================
__global__ void __launch_bounds__(256, 2) mlin_out_mma(float* __restrict__ out) {
    extern __shared__ __align__(16) unsigned dynsmem[];
    unsigned (*As)[128][36] = (unsigned(*)[128][36])dynsmem;
    unsigned (*Bs)[32][136] = (unsigned(*)[32][136])(dynsmem + 3 * 128 * 36);

    const int c = blockIdx.z;
    const float* W = g_wt + 3u * 524288 + (size_t)c * 65536;
    const int g0 = blockIdx.y * 128;
    const int colb = blockIdx.x * 16;
    GEMM_THREAD_IDS

    float C[4][4][4] = {};

#define LOAD_OUT(ST, K0)                                                              \
    {                                                                                 \
        _Pragma("unroll")                                                             \
        for (int i = 0; i < 4; i++) {                                                 \
            const int idx = i * 256 + tid;                                            \
            const int row = idx >> 3, f4 = idx & 7;                                   \
            cp16(&As[ST][row][f4 * 4], W + (size_t)(g0 + row) * 256 + (K0) + f4 * 4); \
        }                                                                             \
        _Pragma("unroll")                                                             \
        for (int i = 0; i < 4; i++) {                                                 \
            const int idx = i * 256 + tid;                                            \
            const int w4 = idx & 1, nl = (idx >> 1) & 15, kb = idx >> 5;              \
            const int n = colb + nl;                                                  \
            const int b = n >> 9, l = n & 511;                                        \
            cp16(&Bs[ST][kb][nl * 8 + w4 * 4],                                        \
                 g_a + ((size_t)(b * 8 + c) * 512 + l) * 2048 +                       \
                     (size_t)((K0) + kb) * 8 + w4 * 4);                               \
        }                                                                             \
        CP_COMMIT;                                                                    \
    }

    PIPE_LOOP(8, LOAD_OUT, FRAG_COMPUTE(st, Bs[st][kk][n], Bs[st][kk + 4][n]))
#undef LOAD_OUT

#pragma unroll
    for (int mi = 0; mi < 4; mi++) {
        const int gr = g0 + wm * 64 + mi * 16 + (lane >> 2);
#pragma unroll
        for (int ni = 0; ni < 4; ni++) {
            const int cc = colb * 8 + wn * 32 + ni * 8 + (lane & 3) * 2;
#pragma unroll
            for (int e = 0; e < 4; e++) {
                const int g = gr + (e >> 1) * 8;
                const int cg = cc + (e & 1);
                const int n = cg >> 3, w = cg & 7;
                const int b = n >> 9, l = n & 511;
                out[(((size_t)(b * 8 + c) * 512 + l) * 256 + g) * 8 + w] = C[mi][ni][e];
            }
        }
    }
}

// =============================================================================
extern "C" void kernel_launch(void* const* d_in, const int* in_sizes, int n_in,
                              void* d_out, int out_size) {
    const float* x    = (const float*)d_in[0];
    const float* prev = (const float*)d_in[1];
    const float* cqw  = (const float*)d_in[2];
    const float* ckw  = (const float*)d_in[3];
    const float* cvw  = (const float*)d_in[4];
    const float* wq   = (const float*)d_in[5];
    const float* wk   = (const float*)d_in[6];
    const float* wv   = (const float*)d_in[7];
    const float* wo   = (const float*)d_in[8];
    float* out = (float*)d_out;
    float* out_qk = out + QK_OFF;

    static bool attr_done = false;
    if (!attr_done) {
        cudaFuncSetAttribute(mlin_qkv_mma, cudaFuncAttributeMaxDynamicSharedMemorySize, PV_SMEM3);
        cudaFuncSetAttribute(qk_mma, cudaFuncAttributeMaxDynamicSharedMemorySize, QK_SMEM3);
        cudaFuncSetAttribute(pv_mma, cudaFuncAttributeMaxDynamicSharedMemorySize, PV_SMEM3);
        cudaFuncSetAttribute(mlin_out_mma, cudaFuncAttributeMaxDynamicSharedMemorySize, PV_SMEM3);
        attr_done = true;
    }

    conv3_kernel<<<dim3(1024, 8), 256>>>(x, cqw, ckw, cvw);
    wcvt_kernel<<<2048, 256>>>(wq, wk, wv, wo);
    mlin_qkv_mma<<<dim3(64, 2, 24), 256, PV_SMEM3>>>();
    qk_mma<<<dim3(4, 4, 128), 256, QK_SMEM3>>>(prev, out_qk);
    softmax_kernel<<<8192, 256>>>(out_qk);
    pv_mma<<<dim3(2, 4, 128), 256, PV_SMEM3>>>();
    mlin_out_mma<<<dim3(64, 2, 8), 256, PV_SMEM3>>>(out);
}